// round 4
// baseline (speedup 1.0000x reference)
#include <cuda_runtime.h>
#include <cstdint>
#include <math.h>

#define B_    16
#define CIN   256
#define COUT  256
#define KW    3
#define L_    4096
#define NR    5
#define CK    768            // CIN*KW
#define MROWS 1280           // NR*COUT
#define BL    (B_ * L_)

// ---------------- scratch (device globals; allocation-free) ----------------
__device__ float g_fr[NR * BL];                 // fr[n][b*L+l]
__device__ float g_A[MROWS * CK];               // tf32 weights [m][ck]
__device__ float g_P[(size_t)B_ * L_ * CK];     // tf32 patches [b][l][ck]

// ---------------- helpers ----------------
__device__ __forceinline__ float to_tf32(float v) {
    uint32_t b;
    asm("cvt.rna.tf32.f32 %0, %1;" : "=r"(b) : "f"(v));
    return __uint_as_float(b);
}
__device__ __forceinline__ void cp16(uint32_t dst, const void* src) {
    asm volatile("cp.async.cg.shared.global [%0], [%1], 16;" :: "r"(dst), "l"(src));
}
__device__ __forceinline__ void cp_commit() {
    asm volatile("cp.async.commit_group;");
}
__device__ __forceinline__ void cp_wait_1() {
    asm volatile("cp.async.wait_group 1;");
}
__device__ __forceinline__ void ldsm4(uint32_t* r, uint32_t addr) {
    asm volatile("ldmatrix.sync.aligned.m8n8.x4.shared.b16 {%0,%1,%2,%3}, [%4];"
                 : "=r"(r[0]), "=r"(r[1]), "=r"(r[2]), "=r"(r[3]) : "r"(addr));
}
__device__ __forceinline__ void mma_tf32(float* d, const uint32_t* a, uint32_t b0, uint32_t b1) {
    asm volatile("mma.sync.aligned.m16n8k8.row.col.f32.tf32.tf32.f32 "
                 "{%0,%1,%2,%3}, {%4,%5,%6,%7}, {%8,%9}, {%0,%1,%2,%3};"
                 : "+f"(d[0]), "+f"(d[1]), "+f"(d[2]), "+f"(d[3])
                 : "r"(a[0]), "r"(a[1]), "r"(a[2]), "r"(a[3]), "r"(b0), "r"(b1));
}

// ---------------------------------------------------------------------------
// prep A: tf32-round weights (already [m][ck] contiguous)
// ---------------------------------------------------------------------------
__global__ void __launch_bounds__(256) prepA_kernel(const float* __restrict__ w) {
    int i = blockIdx.x * 256 + threadIdx.x;
    if (i < MROWS * CK) g_A[i] = to_tf32(w[i]);
}

// ---------------------------------------------------------------------------
// prep P: g_P[b][l][ck] = tf32(x[b][ck/3][l + ck%3 - 2]), causal zero-pad
// ---------------------------------------------------------------------------
__global__ void __launch_bounds__(256) prepP_kernel(const float* __restrict__ x) {
    __shared__ float xs[64][34];
    const int tid = threadIdx.x;
    const int l0 = blockIdx.x * 32;
    const int c0 = blockIdx.y * 64;
    const int b  = blockIdx.z;

    for (int idx = tid; idx < 64 * 34; idx += 256) {
        const int c = idx / 34, j = idx % 34;
        const int gl = l0 - 2 + j;
        xs[c][j] = (gl >= 0) ? x[((size_t)(b * CIN + c0 + c)) * L_ + gl] : 0.0f;
    }
    __syncthreads();

    float* Pb = g_P + ((size_t)b * L_ + l0) * CK + c0 * 3;
    for (int idx = tid; idx < 32 * 192; idx += 256) {
        const int li = idx / 192, q = idx % 192;
        const int c = q / 3, k = q - 3 * c;
        Pb[(size_t)li * CK + q] = to_tf32(xs[c][li + k]);
    }
}

// ---------------------------------------------------------------------------
// controller: 4 l per thread, vector loads, full fp32
// ---------------------------------------------------------------------------
__global__ void __launch_bounds__(128) ctrl_kernel(
    const float* __restrict__ x, const float* __restrict__ cw,
    const float* __restrict__ cb)
{
    __shared__ float sw[CK * NR];
    const int tid = threadIdx.x;
    for (int i = tid; i < CK * NR; i += 128) sw[i] = cw[i];
    __syncthreads();

    const int b  = blockIdx.y;
    const int l4 = (blockIdx.x * 128 + tid) * 4;
    const float* xb = x + (size_t)b * CIN * L_;

    float acc[4][NR];
#pragma unroll
    for (int li = 0; li < 4; li++)
#pragma unroll
        for (int n = 0; n < NR; n++) acc[li][n] = cb[n];

    for (int c = 0; c < CIN; c++) {
        const float* xc = xb + (size_t)c * L_ + l4;
        float v[6];
        if (l4 >= 2) {
            const float2 u = *reinterpret_cast<const float2*>(xc - 2);
            v[0] = u.x; v[1] = u.y;
        } else { v[0] = 0.0f; v[1] = 0.0f; }
        const float4 w4 = *reinterpret_cast<const float4*>(xc);
        v[2] = w4.x; v[3] = w4.y; v[4] = w4.z; v[5] = w4.w;

        const float* wr = &sw[c * 3 * NR];
#pragma unroll
        for (int li = 0; li < 4; li++)
#pragma unroll
            for (int n = 0; n < NR; n++)
                acc[li][n] += v[li] * wr[n] + v[li + 1] * wr[NR + n] + v[li + 2] * wr[2 * NR + n];
    }

#pragma unroll
    for (int li = 0; li < 4; li++) {
        float mx = acc[li][0];
#pragma unroll
        for (int n = 1; n < NR; n++) mx = fmaxf(mx, acc[li][n]);
        float e[NR], s = 0.0f;
#pragma unroll
        for (int n = 0; n < NR; n++) { e[n] = __expf(acc[li][n] - mx); s += e[n]; }
        const float inv = 1.0f / s;
        const size_t bl = (size_t)b * L_ + l4 + li;
#pragma unroll
        for (int n = 0; n < NR; n++) g_fr[(size_t)n * BL + bl] = e[n] * inv;
    }
}

// ---------------------------------------------------------------------------
// Fused GEMM+mix: per block (b, 128 o, 128 l), loop 5 rules inside,
// fold with fr/bias into accout, write final out. 3-stage cp.async pipeline,
// 256 threads (8 warps: 2m x 4n), warp tile 64x32, tf32 mma.sync.
// ---------------------------------------------------------------------------
#define GBK   32
#define KROW  36                       // padded row stride (floats)
#define OPF   (128 * KROW)             // floats per operand tile (4608)
#define STAGEF (2 * OPF)               // floats per stage (A + B)
#define NSTAGE 3
#define KTILES 24                      // CK / GBK
#define TOTIT  (NR * KTILES)           // 120

__global__ void __launch_bounds__(256, 1) gemm_kernel(
    const float* __restrict__ bias,    // (NR, COUT)
    float* __restrict__ out)           // (B, COUT, L)
{
    extern __shared__ float smem[];
    const uint32_t sbase = (uint32_t)__cvta_generic_to_shared(smem);
    float* sfr   = smem + NSTAGE * STAGEF;          // [NR][128] fr
    float* sbias = sfr + NR * 128;                  // [NR][128] bias slice

    const int tid  = threadIdx.x;
    const int lane = tid & 31;
    const int wid  = tid >> 5;
    const int warp_m = wid >> 2;        // 0..1 (64 rows each)
    const int warp_n = wid & 3;         // 0..3 (32 cols each)

    const int b  = blockIdx.z;
    const int o0 = blockIdx.y * 128;
    const int l0 = blockIdx.x * 128;

    const float* Pg = g_P + ((size_t)b * L_ + l0) * CK;

    // fill fr / bias slices
    for (int i = tid; i < NR * 128; i += 256) {
        const int n = i >> 7, j = i & 127;
        sfr[i]   = g_fr[(size_t)n * BL + (size_t)b * L_ + l0 + j];
        sbias[i] = bias[n * COUT + o0 + j];
    }

    // per-thread loader coords: 1024 chunks per operand, 4 per thread
    // idx = tid + i*256 ; row = idx>>3 ; kc = (idx&7)*4
    auto load_tile = [&](int it) {
        const int stage = it % NSTAGE;
        const int rule  = it / KTILES;
        const int kt    = (it - rule * KTILES) * GBK;
        const float* Ag = g_A + (size_t)(rule * COUT + o0) * CK + kt;
        const float* Bg = Pg + kt;
        const uint32_t sA = sbase + (uint32_t)(stage * STAGEF) * 4;
        const uint32_t sB = sA + (uint32_t)OPF * 4;
#pragma unroll
        for (int i = 0; i < 4; i++) {
            const int idx = tid + i * 256;
            const int row = idx >> 3;
            const int kc  = (idx & 7) * 4;
            const uint32_t soff = (uint32_t)(row * KROW + kc) * 4;
            cp16(sA + soff, Ag + (size_t)row * CK + kc);
            cp16(sB + soff, Bg + (size_t)row * CK + kc);
        }
        cp_commit();
    };

    float acc[4][4][4];      // [mt][nt][reg] : Y for current rule
    float accout[4][4][4];   // final weighted output
#pragma unroll
    for (int mt = 0; mt < 4; mt++)
#pragma unroll
        for (int nt = 0; nt < 4; nt++)
#pragma unroll
            for (int r = 0; r < 4; r++) { acc[mt][nt][r] = 0.0f; accout[mt][nt][r] = 0.0f; }

    // prologue: stages 0..NSTAGE-2
    load_tile(0);
    load_tile(1);

    const int arow = warp_m * 64 + (lane & 15);
    const int brow = warp_n * 32 + (lane & 15);
    const int koff = (lane >> 4) * 4;
    const int lbase = warp_n * 32 + (lane & 3) * 2;   // within 128-l tile
    const int obase = warp_m * 64 + (lane >> 2);      // within 128-o tile

    for (int it = 0; it < TOTIT; it++) {
        cp_wait_1();
        __syncthreads();
        if (it + NSTAGE - 1 < TOTIT) load_tile(it + NSTAGE - 1);
        cp_commit();   // keep one group per iteration (empty at tail)

        const int stage = it % NSTAGE;
        const uint32_t sA = sbase + (uint32_t)(stage * STAGEF) * 4;
        const uint32_t sB = sA + (uint32_t)OPF * 4;

#pragma unroll
        for (int ks = 0; ks < 4; ks++) {
            const int k0 = ks * 8 + koff;
            uint32_t a[4][4];
#pragma unroll
            for (int mt = 0; mt < 4; mt++)
                ldsm4(a[mt], sA + (uint32_t)((arow + mt * 16) * KROW + k0) * 4);
            uint32_t bb[2][4];
#pragma unroll
            for (int np = 0; np < 2; np++)
                ldsm4(bb[np], sB + (uint32_t)((brow + np * 16) * KROW + k0) * 4);
#pragma unroll
            for (int mt = 0; mt < 4; mt++)
#pragma unroll
                for (int np = 0; np < 2; np++) {
                    mma_tf32(acc[mt][2 * np],     a[mt], bb[np][0], bb[np][2]);
                    mma_tf32(acc[mt][2 * np + 1], a[mt], bb[np][1], bb[np][3]);
                }
        }

        // end of a rule: fold into accout with fr & bias, reset acc
        if ((it + 1) % KTILES == 0) {
            const int n = it / KTILES;
            float fr0[4], fr1[4], bi0[4], bi1[4];
#pragma unroll
            for (int nt = 0; nt < 4; nt++) {
                fr0[nt] = sfr[n * 128 + lbase + nt * 8];
                fr1[nt] = sfr[n * 128 + lbase + nt * 8 + 1];
            }
#pragma unroll
            for (int mt = 0; mt < 4; mt++) {
                bi0[mt] = sbias[n * 128 + obase + mt * 16];
                bi1[mt] = sbias[n * 128 + obase + mt * 16 + 8];
            }
#pragma unroll
            for (int mt = 0; mt < 4; mt++)
#pragma unroll
                for (int nt = 0; nt < 4; nt++) {
                    accout[mt][nt][0] += fr0[nt] * (acc[mt][nt][0] + bi0[mt]);
                    accout[mt][nt][1] += fr1[nt] * (acc[mt][nt][1] + bi0[mt]);
                    accout[mt][nt][2] += fr0[nt] * (acc[mt][nt][2] + bi1[mt]);
                    accout[mt][nt][3] += fr1[nt] * (acc[mt][nt][3] + bi1[mt]);
                    acc[mt][nt][0] = 0.0f; acc[mt][nt][1] = 0.0f;
                    acc[mt][nt][2] = 0.0f; acc[mt][nt][3] = 0.0f;
                }
        }
        __syncthreads();
    }

    // write final output
    float* ob = out + ((size_t)b * COUT + o0) * L_ + l0;
#pragma unroll
    for (int mt = 0; mt < 4; mt++) {
#pragma unroll
        for (int nt = 0; nt < 4; nt++) {
            const int o = obase + mt * 16;
            const int l = lbase + nt * 8;
            float2* p0 = reinterpret_cast<float2*>(ob + (size_t)o * L_ + l);
            float2* p1 = reinterpret_cast<float2*>(ob + (size_t)(o + 8) * L_ + l);
            *p0 = make_float2(accout[mt][nt][0], accout[mt][nt][1]);
            *p1 = make_float2(accout[mt][nt][2], accout[mt][nt][3]);
        }
    }
}

#define GEMM_SMEM ((NSTAGE * STAGEF + 2 * NR * 128) * 4)

// ---------------------------------------------------------------------------
// launch
// ---------------------------------------------------------------------------
extern "C" void kernel_launch(void* const* d_in, const int* in_sizes, int n_in,
                              void* d_out, int out_size) {
    const float* x  = (const float*)d_in[0];
    const float* bk = (const float*)d_in[1];
    const float* bb = (const float*)d_in[2];
    const float* cw = (const float*)d_in[3];
    const float* cb = (const float*)d_in[4];
    float* out = (float*)d_out;

    static int smem_set = 0;
    if (!smem_set) {
        cudaFuncSetAttribute(gemm_kernel, cudaFuncAttributeMaxDynamicSharedMemorySize,
                             GEMM_SMEM);
        smem_set = 1;
    }

    prepA_kernel<<<(MROWS * CK + 255) / 256, 256>>>(bk);
    prepP_kernel<<<dim3(L_ / 32, CIN / 64, B_), 256>>>(x);
    ctrl_kernel<<<dim3(L_ / 512, B_), 128>>>(x, cw, cb);
    gemm_kernel<<<dim3(L_ / 128, COUT / 128, B_), 256, GEMM_SMEM>>>(bb, out);
}

// round 5
// speedup vs baseline: 1.0139x; 1.0139x over previous
#include <cuda_runtime.h>
#include <cstdint>
#include <math.h>

#define B_    16
#define CIN   256
#define COUT  256
#define KW    3
#define L_    4096
#define NR    5
#define CK    768            // CIN*KW
#define MROWS 1280           // NR*COUT
#define BL    (B_ * L_)

// ---------------- scratch (device globals; allocation-free) ----------------
__device__ float g_fr[NR * BL];                 // fr[n][b*L+l]
__device__ float g_A[MROWS * CK];               // tf32 weights [m][ck]
__device__ float g_P[(size_t)B_ * L_ * CK];     // tf32 patches [b][l][ck]

// ---------------- helpers ----------------
__device__ __forceinline__ float to_tf32(float v) {
    uint32_t b;
    asm("cvt.rna.tf32.f32 %0, %1;" : "=r"(b) : "f"(v));
    return __uint_as_float(b);
}
__device__ __forceinline__ void cp16(uint32_t dst, const void* src) {
    asm volatile("cp.async.cg.shared.global [%0], [%1], 16;" :: "r"(dst), "l"(src));
}
__device__ __forceinline__ void cp_commit() {
    asm volatile("cp.async.commit_group;");
}
__device__ __forceinline__ void cp_wait_1() {
    asm volatile("cp.async.wait_group 1;");
}
__device__ __forceinline__ void ldsm4(uint32_t* r, uint32_t addr) {
    asm volatile("ldmatrix.sync.aligned.m8n8.x4.shared.b16 {%0,%1,%2,%3}, [%4];"
                 : "=r"(r[0]), "=r"(r[1]), "=r"(r[2]), "=r"(r[3]) : "r"(addr));
}
__device__ __forceinline__ void mma_tf32(float* d, const uint32_t* a, uint32_t b0, uint32_t b1) {
    asm volatile("mma.sync.aligned.m16n8k8.row.col.f32.tf32.tf32.f32 "
                 "{%0,%1,%2,%3}, {%4,%5,%6,%7}, {%8,%9}, {%0,%1,%2,%3};"
                 : "+f"(d[0]), "+f"(d[1]), "+f"(d[2]), "+f"(d[3])
                 : "r"(a[0]), "r"(a[1]), "r"(a[2]), "r"(a[3]), "r"(b0), "r"(b1));
}

// ---------------------------------------------------------------------------
// prep A: tf32-round weights
// ---------------------------------------------------------------------------
__global__ void __launch_bounds__(256) prepA_kernel(const float* __restrict__ w) {
    int i = blockIdx.x * 256 + threadIdx.x;
    if (i < MROWS * CK) g_A[i] = to_tf32(w[i]);
}

// ---------------------------------------------------------------------------
// prep P: g_P[b][l][ck] = tf32(x[b][ck/3][l + ck%3 - 2]), causal zero-pad
// ---------------------------------------------------------------------------
__global__ void __launch_bounds__(256) prepP_kernel(const float* __restrict__ x) {
    __shared__ float xs[64][34];
    const int tid = threadIdx.x;
    const int l0 = blockIdx.x * 32;
    const int c0 = blockIdx.y * 64;
    const int b  = blockIdx.z;

    for (int idx = tid; idx < 64 * 34; idx += 256) {
        const int c = idx / 34, j = idx % 34;
        const int gl = l0 - 2 + j;
        xs[c][j] = (gl >= 0) ? x[((size_t)(b * CIN + c0 + c)) * L_ + gl] : 0.0f;
    }
    __syncthreads();

    float* Pb = g_P + ((size_t)b * L_ + l0) * CK + c0 * 3;
    for (int idx = tid; idx < 32 * 192; idx += 256) {
        const int li = idx / 192, q = idx % 192;
        const int c = q / 3, k = q - 3 * c;
        Pb[(size_t)li * CK + q] = to_tf32(xs[c][li + k]);
    }
}

// ---------------------------------------------------------------------------
// controller: 4 l per thread, vector loads, full fp32
// ---------------------------------------------------------------------------
__global__ void __launch_bounds__(128) ctrl_kernel(
    const float* __restrict__ x, const float* __restrict__ cw,
    const float* __restrict__ cb)
{
    __shared__ float sw[CK * NR];
    const int tid = threadIdx.x;
    for (int i = tid; i < CK * NR; i += 128) sw[i] = cw[i];
    __syncthreads();

    const int b  = blockIdx.y;
    const int l4 = (blockIdx.x * 128 + tid) * 4;
    const float* xb = x + (size_t)b * CIN * L_;

    float acc[4][NR];
#pragma unroll
    for (int li = 0; li < 4; li++)
#pragma unroll
        for (int n = 0; n < NR; n++) acc[li][n] = cb[n];

    for (int c = 0; c < CIN; c++) {
        const float* xc = xb + (size_t)c * L_ + l4;
        float v[6];
        if (l4 >= 2) {
            const float2 u = *reinterpret_cast<const float2*>(xc - 2);
            v[0] = u.x; v[1] = u.y;
        } else { v[0] = 0.0f; v[1] = 0.0f; }
        const float4 w4 = *reinterpret_cast<const float4*>(xc);
        v[2] = w4.x; v[3] = w4.y; v[4] = w4.z; v[5] = w4.w;

        const float* wr = &sw[c * 3 * NR];
#pragma unroll
        for (int li = 0; li < 4; li++)
#pragma unroll
            for (int n = 0; n < NR; n++)
                acc[li][n] += v[li] * wr[n] + v[li + 1] * wr[NR + n] + v[li + 2] * wr[2 * NR + n];
    }

#pragma unroll
    for (int li = 0; li < 4; li++) {
        float mx = acc[li][0];
#pragma unroll
        for (int n = 1; n < NR; n++) mx = fmaxf(mx, acc[li][n]);
        float e[NR], s = 0.0f;
#pragma unroll
        for (int n = 0; n < NR; n++) { e[n] = __expf(acc[li][n] - mx); s += e[n]; }
        const float inv = 1.0f / s;
        const size_t bl = (size_t)b * L_ + l4 + li;
#pragma unroll
        for (int n = 0; n < NR; n++) g_fr[(size_t)n * BL + bl] = e[n] * inv;
    }
}

// ---------------------------------------------------------------------------
// Fused GEMM+mix: per block (b, 128 o, 128 l), rules looped inside k-pipeline.
// 3-stage cp.async ring, ONE commit group per iteration, ONE sync per
// iteration (prefetch issued after the sync). 256 threads, warp tile 64x32.
// ---------------------------------------------------------------------------
#define GBK   32
#define KROW  36                       // padded row stride (floats)
#define OPF   (128 * KROW)             // floats per operand tile (4608)
#define STAGEF (2 * OPF)               // floats per stage (A + B)
#define NSTAGE 3
#define KTILES 24                      // CK / GBK
#define TOTIT  (NR * KTILES)           // 120

__global__ void __launch_bounds__(256, 1) gemm_kernel(
    const float* __restrict__ bias,    // (NR, COUT)
    float* __restrict__ out)           // (B, COUT, L)
{
    extern __shared__ float smem[];
    const uint32_t sbase = (uint32_t)__cvta_generic_to_shared(smem);
    float* sfr   = smem + NSTAGE * STAGEF;          // [NR][128] fr
    float* sbias = sfr + NR * 128;                  // [NR][128] bias slice

    const int tid  = threadIdx.x;
    const int lane = tid & 31;
    const int wid  = tid >> 5;
    const int warp_m = wid >> 2;        // 0..1 (64 rows each)
    const int warp_n = wid & 3;         // 0..3 (32 cols each)

    const int b  = blockIdx.z;
    const int o0 = blockIdx.y * 128;
    const int l0 = blockIdx.x * 128;

    const float* Pg = g_P + ((size_t)b * L_ + l0) * CK;

    // fill fr / bias slices (covered by the first in-loop __syncthreads)
    for (int i = tid; i < NR * 128; i += 256) {
        const int n = i >> 7, j = i & 127;
        sfr[i]   = g_fr[(size_t)n * BL + (size_t)b * L_ + l0 + j];
        sbias[i] = bias[n * COUT + o0 + j];
    }

    // per-thread loader coords: 1024 16B chunks per operand, 4 per thread
    auto load_tile = [&](int it) {
        const int stage = it % NSTAGE;
        const int rule  = it / KTILES;
        const int kt    = (it - rule * KTILES) * GBK;
        const float* Ag = g_A + (size_t)(rule * COUT + o0) * CK + kt;
        const float* Bg = Pg + kt;
        const uint32_t sA = sbase + (uint32_t)(stage * STAGEF) * 4;
        const uint32_t sB = sA + (uint32_t)OPF * 4;
#pragma unroll
        for (int i = 0; i < 4; i++) {
            const int idx = tid + i * 256;
            const int row = idx >> 3;
            const int kc  = (idx & 7) * 4;
            const uint32_t soff = (uint32_t)(row * KROW + kc) * 4;
            cp16(sA + soff, Ag + (size_t)row * CK + kc);
            cp16(sB + soff, Bg + (size_t)row * CK + kc);
        }
        cp_commit();
    };

    float acc[4][4][4];      // current rule's conv accumulator
    float accout[4][4][4];   // final weighted output
#pragma unroll
    for (int mt = 0; mt < 4; mt++)
#pragma unroll
        for (int nt = 0; nt < 4; nt++)
#pragma unroll
            for (int r = 0; r < 4; r++) { acc[mt][nt][r] = 0.0f; accout[mt][nt][r] = 0.0f; }

    // prologue: 2 stages in flight
    load_tile(0);
    load_tile(1);

    const int arow = warp_m * 64 + (lane & 15);
    const int brow = warp_n * 32 + (lane & 15);
    const int koff = (lane >> 4) * 4;
    const int lbase = warp_n * 32 + (lane & 3) * 2;
    const int obase = warp_m * 64 + (lane >> 2);

    for (int it = 0; it < TOTIT; it++) {
        cp_wait_1();           // stage it%3 ready; ≤1 younger group pending
        __syncthreads();       // all warps past iter it-1 reads

        // exactly ONE commit group per iteration (empty in the tail keeps
        // the wait_group accounting uniform)
        if (it + NSTAGE - 1 < TOTIT) load_tile(it + NSTAGE - 1);
        else cp_commit();

        const int stage = it % NSTAGE;
        const uint32_t sA = sbase + (uint32_t)(stage * STAGEF) * 4;
        const uint32_t sB = sA + (uint32_t)OPF * 4;

#pragma unroll
        for (int ks = 0; ks < 4; ks++) {
            const int k0 = ks * 8 + koff;
            uint32_t a[4][4];
#pragma unroll
            for (int mt = 0; mt < 4; mt++)
                ldsm4(a[mt], sA + (uint32_t)((arow + mt * 16) * KROW + k0) * 4);
            uint32_t bb[2][4];
#pragma unroll
            for (int np = 0; np < 2; np++)
                ldsm4(bb[np], sB + (uint32_t)((brow + np * 16) * KROW + k0) * 4);
#pragma unroll
            for (int mt = 0; mt < 4; mt++)
#pragma unroll
                for (int np = 0; np < 2; np++) {
                    mma_tf32(acc[mt][2 * np],     a[mt], bb[np][0], bb[np][2]);
                    mma_tf32(acc[mt][2 * np + 1], a[mt], bb[np][1], bb[np][3]);
                }
        }

        // end of a rule: fold into accout with fr & bias, reset acc
        if ((it + 1) % KTILES == 0) {
            const int n = it / KTILES;
            float fr0[4], fr1[4], bi0[4], bi1[4];
#pragma unroll
            for (int nt = 0; nt < 4; nt++) {
                fr0[nt] = sfr[n * 128 + lbase + nt * 8];
                fr1[nt] = sfr[n * 128 + lbase + nt * 8 + 1];
            }
#pragma unroll
            for (int mt = 0; mt < 4; mt++) {
                bi0[mt] = sbias[n * 128 + obase + mt * 16];
                bi1[mt] = sbias[n * 128 + obase + mt * 16 + 8];
            }
#pragma unroll
            for (int mt = 0; mt < 4; mt++)
#pragma unroll
                for (int nt = 0; nt < 4; nt++) {
                    accout[mt][nt][0] += fr0[nt] * (acc[mt][nt][0] + bi0[mt]);
                    accout[mt][nt][1] += fr1[nt] * (acc[mt][nt][1] + bi0[mt]);
                    accout[mt][nt][2] += fr0[nt] * (acc[mt][nt][2] + bi1[mt]);
                    accout[mt][nt][3] += fr1[nt] * (acc[mt][nt][3] + bi1[mt]);
                    acc[mt][nt][0] = 0.0f; acc[mt][nt][1] = 0.0f;
                    acc[mt][nt][2] = 0.0f; acc[mt][nt][3] = 0.0f;
                }
        }
    }

    // write final output
    float* ob = out + ((size_t)b * COUT + o0) * L_ + l0;
#pragma unroll
    for (int mt = 0; mt < 4; mt++) {
#pragma unroll
        for (int nt = 0; nt < 4; nt++) {
            const int o = obase + mt * 16;
            const int l = lbase + nt * 8;
            float2* p0 = reinterpret_cast<float2*>(ob + (size_t)o * L_ + l);
            float2* p1 = reinterpret_cast<float2*>(ob + (size_t)(o + 8) * L_ + l);
            *p0 = make_float2(accout[mt][nt][0], accout[mt][nt][1]);
            *p1 = make_float2(accout[mt][nt][2], accout[mt][nt][3]);
        }
    }
}

#define GEMM_SMEM ((NSTAGE * STAGEF + 2 * NR * 128) * 4)

// ---------------------------------------------------------------------------
// launch
// ---------------------------------------------------------------------------
extern "C" void kernel_launch(void* const* d_in, const int* in_sizes, int n_in,
                              void* d_out, int out_size) {
    const float* x  = (const float*)d_in[0];
    const float* bk = (const float*)d_in[1];
    const float* bb = (const float*)d_in[2];
    const float* cw = (const float*)d_in[3];
    const float* cb = (const float*)d_in[4];
    float* out = (float*)d_out;

    static int smem_set = 0;
    if (!smem_set) {
        cudaFuncSetAttribute(gemm_kernel, cudaFuncAttributeMaxDynamicSharedMemorySize,
                             GEMM_SMEM);
        smem_set = 1;
    }

    prepA_kernel<<<(MROWS * CK + 255) / 256, 256>>>(bk);
    prepP_kernel<<<dim3(L_ / 32, CIN / 64, B_), 256>>>(x);
    ctrl_kernel<<<dim3(L_ / 512, B_), 128>>>(x, cw, cb);
    gemm_kernel<<<dim3(L_ / 128, COUT / 128, B_), 256, GEMM_SMEM>>>(bb, out);
}

// round 6
// speedup vs baseline: 1.0751x; 1.0603x over previous
#include <cuda_runtime.h>
#include <cstdint>
#include <math.h>

#define B_    16
#define CIN   256
#define COUT  256
#define KW    3
#define L_    4096
#define NR    5
#define CK    768            // CIN*KW
#define MROWS 1280           // NR*COUT
#define BL    (B_ * L_)

// ---------------- scratch (device globals; allocation-free) ----------------
__device__ float g_fr[NR * BL];                 // fr[n][b*L+l]
__device__ float g_A[MROWS * CK];               // tf32 weights [m][ck]
__device__ float g_P[(size_t)B_ * L_ * CK];     // tf32 patches [b][l][ck]

// ---------------- helpers ----------------
__device__ __forceinline__ float to_tf32(float v) {
    uint32_t b;
    asm("cvt.rna.tf32.f32 %0, %1;" : "=r"(b) : "f"(v));
    return __uint_as_float(b);
}
__device__ __forceinline__ void cp16(uint32_t dst, const void* src) {
    asm volatile("cp.async.cg.shared.global [%0], [%1], 16;" :: "r"(dst), "l"(src));
}
__device__ __forceinline__ void cp_commit() {
    asm volatile("cp.async.commit_group;");
}
__device__ __forceinline__ void cp_wait_1() {
    asm volatile("cp.async.wait_group 1;");
}
__device__ __forceinline__ void ldsm4(uint32_t* r, uint32_t addr) {
    asm volatile("ldmatrix.sync.aligned.m8n8.x4.shared.b16 {%0,%1,%2,%3}, [%4];"
                 : "=r"(r[0]), "=r"(r[1]), "=r"(r[2]), "=r"(r[3]) : "r"(addr));
}
__device__ __forceinline__ void mma_tf32(float* d, const uint32_t* a, uint32_t b0, uint32_t b1) {
    asm volatile("mma.sync.aligned.m16n8k8.row.col.f32.tf32.tf32.f32 "
                 "{%0,%1,%2,%3}, {%4,%5,%6,%7}, {%8,%9}, {%0,%1,%2,%3};"
                 : "+f"(d[0]), "+f"(d[1]), "+f"(d[2]), "+f"(d[3])
                 : "r"(a[0]), "r"(a[1]), "r"(a[2]), "r"(a[3]), "r"(b0), "r"(b1));
}

// ---------------------------------------------------------------------------
// prep A: tf32-round weights
// ---------------------------------------------------------------------------
__global__ void __launch_bounds__(256) prepA_kernel(const float* __restrict__ w) {
    int i = blockIdx.x * 256 + threadIdx.x;
    if (i < MROWS * CK) g_A[i] = to_tf32(w[i]);
}

// ---------------------------------------------------------------------------
// prep P: g_P[b][l][ck] = tf32(x[b][ck/3][l + ck%3 - 2]), causal zero-pad
// ---------------------------------------------------------------------------
__global__ void __launch_bounds__(256) prepP_kernel(const float* __restrict__ x) {
    __shared__ float xs[64][34];
    const int tid = threadIdx.x;
    const int l0 = blockIdx.x * 32;
    const int c0 = blockIdx.y * 64;
    const int b  = blockIdx.z;

    for (int idx = tid; idx < 64 * 34; idx += 256) {
        const int c = idx / 34, j = idx % 34;
        const int gl = l0 - 2 + j;
        xs[c][j] = (gl >= 0) ? x[((size_t)(b * CIN + c0 + c)) * L_ + gl] : 0.0f;
    }
    __syncthreads();

    float* Pb = g_P + ((size_t)b * L_ + l0) * CK + c0 * 3;
    for (int idx = tid; idx < 32 * 192; idx += 256) {
        const int li = idx / 192, q = idx % 192;
        const int c = q / 3, k = q - 3 * c;
        Pb[(size_t)li * CK + q] = to_tf32(xs[c][li + k]);
    }
}

// ---------------------------------------------------------------------------
// controller: 4 l per thread, vector loads, full fp32
// ---------------------------------------------------------------------------
__global__ void __launch_bounds__(128) ctrl_kernel(
    const float* __restrict__ x, const float* __restrict__ cw,
    const float* __restrict__ cb)
{
    __shared__ float sw[CK * NR];
    const int tid = threadIdx.x;
    for (int i = tid; i < CK * NR; i += 128) sw[i] = cw[i];
    __syncthreads();

    const int b  = blockIdx.y;
    const int l4 = (blockIdx.x * 128 + tid) * 4;
    const float* xb = x + (size_t)b * CIN * L_;

    float acc[4][NR];
#pragma unroll
    for (int li = 0; li < 4; li++)
#pragma unroll
        for (int n = 0; n < NR; n++) acc[li][n] = cb[n];

    for (int c = 0; c < CIN; c++) {
        const float* xc = xb + (size_t)c * L_ + l4;
        float v[6];
        if (l4 >= 2) {
            const float2 u = *reinterpret_cast<const float2*>(xc - 2);
            v[0] = u.x; v[1] = u.y;
        } else { v[0] = 0.0f; v[1] = 0.0f; }
        const float4 w4 = *reinterpret_cast<const float4*>(xc);
        v[2] = w4.x; v[3] = w4.y; v[4] = w4.z; v[5] = w4.w;

        const float* wr = &sw[c * 3 * NR];
#pragma unroll
        for (int li = 0; li < 4; li++)
#pragma unroll
            for (int n = 0; n < NR; n++)
                acc[li][n] += v[li] * wr[n] + v[li + 1] * wr[NR + n] + v[li + 2] * wr[2 * NR + n];
    }

#pragma unroll
    for (int li = 0; li < 4; li++) {
        float mx = acc[li][0];
#pragma unroll
        for (int n = 1; n < NR; n++) mx = fmaxf(mx, acc[li][n]);
        float e[NR], s = 0.0f;
#pragma unroll
        for (int n = 0; n < NR; n++) { e[n] = __expf(acc[li][n] - mx); s += e[n]; }
        const float inv = 1.0f / s;
        const size_t bl = (size_t)b * L_ + l4 + li;
#pragma unroll
        for (int n = 0; n < NR; n++) g_fr[(size_t)n * BL + bl] = e[n] * inv;
    }
}

// ---------------------------------------------------------------------------
// Fused GEMM+mix: 512 threads, 16 warps (4m x 4n), warp tile 32x32.
// Block tile (b, 128 o, 128 l); rules looped inside the k-pipeline.
// 3-stage cp.async ring, one commit group / iter, one sync / iter.
// Low per-thread registers (acc 32 + accout 32) -> 16 warps resident.
// ---------------------------------------------------------------------------
#define GBK   32
#define KROW  36                       // padded row stride (floats)
#define OPF   (128 * KROW)             // floats per operand tile (4608)
#define STAGEF (2 * OPF)               // floats per stage (A + B)
#define NSTAGE 3
#define KTILES 24                      // CK / GBK
#define TOTIT  (NR * KTILES)           // 120
#define NTHR  512

__global__ void __launch_bounds__(NTHR, 1) gemm_kernel(
    const float* __restrict__ bias,    // (NR, COUT)
    float* __restrict__ out)           // (B, COUT, L)
{
    extern __shared__ float smem[];
    const uint32_t sbase = (uint32_t)__cvta_generic_to_shared(smem);
    float* sfr   = smem + NSTAGE * STAGEF;          // [NR][128] fr (l slice)
    float* sbias = sfr + NR * 128;                  // [NR][128] bias (o slice)

    const int tid  = threadIdx.x;
    const int lane = tid & 31;
    const int wid  = tid >> 5;
    const int warp_m = wid >> 2;        // 0..3 (32 rows each)
    const int warp_n = wid & 3;         // 0..3 (32 cols each)

    const int b  = blockIdx.z;
    const int o0 = blockIdx.y * 128;
    const int l0 = blockIdx.x * 128;

    const float* Pg = g_P + ((size_t)b * L_ + l0) * CK;

    // fill fr / bias slices (first in-loop __syncthreads covers them)
    for (int i = tid; i < NR * 128; i += NTHR) {
        const int n = i >> 7, j = i & 127;
        sfr[i]   = g_fr[(size_t)n * BL + (size_t)b * L_ + l0 + j];
        sbias[i] = bias[n * COUT + o0 + j];
    }

    // per-thread loader: 1024 16B chunks per operand, 2 per thread each
    auto load_tile = [&](int it) {
        const int stage = it % NSTAGE;
        const int rule  = it / KTILES;
        const int kt    = (it - rule * KTILES) * GBK;
        const float* Ag = g_A + (size_t)(rule * COUT + o0) * CK + kt;
        const float* Bg = Pg + kt;
        const uint32_t sA = sbase + (uint32_t)(stage * STAGEF) * 4;
        const uint32_t sB = sA + (uint32_t)OPF * 4;
#pragma unroll
        for (int i = 0; i < 2; i++) {
            const int idx = tid + i * NTHR;
            const int row = idx >> 3;
            const int kc  = (idx & 7) * 4;
            const uint32_t soff = (uint32_t)(row * KROW + kc) * 4;
            cp16(sA + soff, Ag + (size_t)row * CK + kc);
            cp16(sB + soff, Bg + (size_t)row * CK + kc);
        }
        cp_commit();
    };

    float acc[2][4][4];      // current rule's conv accumulator (32 regs)
    float accout[2][4][4];   // weighted output accumulator (32 regs)
#pragma unroll
    for (int mt = 0; mt < 2; mt++)
#pragma unroll
        for (int nt = 0; nt < 4; nt++)
#pragma unroll
            for (int r = 0; r < 4; r++) { acc[mt][nt][r] = 0.0f; accout[mt][nt][r] = 0.0f; }

    // prologue
    load_tile(0);
    load_tile(1);

    const int arow = warp_m * 32 + (lane & 15);
    const int brow = warp_n * 32 + (lane & 15);
    const int koff = (lane >> 4) * 4;
    const int lbase = warp_n * 32 + (lane & 3) * 2;
    const int obase = warp_m * 32 + (lane >> 2);

    for (int it = 0; it < TOTIT; it++) {
        cp_wait_1();           // stage it%3 ready
        __syncthreads();       // everyone done reading stage (it+2)%3's old data

        if (it + NSTAGE - 1 < TOTIT) load_tile(it + NSTAGE - 1);
        else cp_commit();      // keep exactly one group per iteration

        const int stage = it % NSTAGE;
        const uint32_t sA = sbase + (uint32_t)(stage * STAGEF) * 4;
        const uint32_t sB = sA + (uint32_t)OPF * 4;

#pragma unroll
        for (int ks = 0; ks < 4; ks++) {
            const int k0 = ks * 8 + koff;
            uint32_t a[2][4];
#pragma unroll
            for (int mt = 0; mt < 2; mt++)
                ldsm4(a[mt], sA + (uint32_t)((arow + mt * 16) * KROW + k0) * 4);
            uint32_t bb[2][4];
#pragma unroll
            for (int np = 0; np < 2; np++)
                ldsm4(bb[np], sB + (uint32_t)((brow + np * 16) * KROW + k0) * 4);
#pragma unroll
            for (int mt = 0; mt < 2; mt++)
#pragma unroll
                for (int np = 0; np < 2; np++) {
                    mma_tf32(acc[mt][2 * np],     a[mt], bb[np][0], bb[np][2]);
                    mma_tf32(acc[mt][2 * np + 1], a[mt], bb[np][1], bb[np][3]);
                }
        }

        // end of a rule: fold into accout with fr & bias, reset acc
        if ((it + 1) % KTILES == 0) {
            const int n = it / KTILES;
            float fr0[4], fr1[4], bi0[2], bi1[2];
#pragma unroll
            for (int nt = 0; nt < 4; nt++) {
                fr0[nt] = sfr[n * 128 + lbase + nt * 8];
                fr1[nt] = sfr[n * 128 + lbase + nt * 8 + 1];
            }
#pragma unroll
            for (int mt = 0; mt < 2; mt++) {
                bi0[mt] = sbias[n * 128 + obase + mt * 16];
                bi1[mt] = sbias[n * 128 + obase + mt * 16 + 8];
            }
#pragma unroll
            for (int mt = 0; mt < 2; mt++)
#pragma unroll
                for (int nt = 0; nt < 4; nt++) {
                    accout[mt][nt][0] += fr0[nt] * (acc[mt][nt][0] + bi0[mt]);
                    accout[mt][nt][1] += fr1[nt] * (acc[mt][nt][1] + bi0[mt]);
                    accout[mt][nt][2] += fr0[nt] * (acc[mt][nt][2] + bi1[mt]);
                    accout[mt][nt][3] += fr1[nt] * (acc[mt][nt][3] + bi1[mt]);
                    acc[mt][nt][0] = 0.0f; acc[mt][nt][1] = 0.0f;
                    acc[mt][nt][2] = 0.0f; acc[mt][nt][3] = 0.0f;
                }
        }
    }

    // write final output
    float* ob = out + ((size_t)b * COUT + o0) * L_ + l0;
#pragma unroll
    for (int mt = 0; mt < 2; mt++) {
#pragma unroll
        for (int nt = 0; nt < 4; nt++) {
            const int o = obase + mt * 16;
            const int l = lbase + nt * 8;
            float2* p0 = reinterpret_cast<float2*>(ob + (size_t)o * L_ + l);
            float2* p1 = reinterpret_cast<float2*>(ob + (size_t)(o + 8) * L_ + l);
            *p0 = make_float2(accout[mt][nt][0], accout[mt][nt][1]);
            *p1 = make_float2(accout[mt][nt][2], accout[mt][nt][3]);
        }
    }
}

#define GEMM_SMEM ((NSTAGE * STAGEF + 2 * NR * 128) * 4)

// ---------------------------------------------------------------------------
// launch
// ---------------------------------------------------------------------------
extern "C" void kernel_launch(void* const* d_in, const int* in_sizes, int n_in,
                              void* d_out, int out_size) {
    const float* x  = (const float*)d_in[0];
    const float* bk = (const float*)d_in[1];
    const float* bb = (const float*)d_in[2];
    const float* cw = (const float*)d_in[3];
    const float* cb = (const float*)d_in[4];
    float* out = (float*)d_out;

    static int smem_set = 0;
    if (!smem_set) {
        cudaFuncSetAttribute(gemm_kernel, cudaFuncAttributeMaxDynamicSharedMemorySize,
                             GEMM_SMEM);
        smem_set = 1;
    }

    prepA_kernel<<<(MROWS * CK + 255) / 256, 256>>>(bk);
    prepP_kernel<<<dim3(L_ / 32, CIN / 64, B_), 256>>>(x);
    ctrl_kernel<<<dim3(L_ / 512, B_), 128>>>(x, cw, cb);
    gemm_kernel<<<dim3(L_ / 128, COUT / 128, B_), NTHR, GEMM_SMEM>>>(bb, out);
}